// round 4
// baseline (speedup 1.0000x reference)
#include <cuda_runtime.h>
#include <math.h>

#define BB 128
#define TT 64
#define EE 512
#define HH 512
#define VV 10000
#define FIN 2048
#define TB (TT*BB)   /* 8192 */

// ---------------- scratch (static device globals; no runtime alloc) ----------------
__device__ float g_f[BB*EE];          // fc output pre-BN
__device__ float g_feats[BB*EE];      // BN output
__device__ float g_x[TT*BB*EE];       // per-step inputs x_t
__device__ float g_h[BB*HH];          // recurrent state
__device__ float g_al[BB*HH];         // attn logits (atomic target)
__device__ float g_aw[BB*HH];         // attn weights (softmax)
__device__ float g_inp[BB*HH];        // comb output (atomic target)
__device__ float g_gh[BB*3*HH];       // Whh gemm (atomic target)
__device__ float g_gx[BB*3*HH];       // Wih gemm (atomic target)
__device__ float g_packed[TB*HH];     // time-major hidden states

__device__ __forceinline__ float4 ld4(const float* p){ return *(const float4*)p; }

// mode 0: A0 row-major [128,K]
// mode 1: concat(x=A0[128,512], g_h)
// mode 2: concat(x=A0[128,512], g_feats*g_aw)
__device__ __forceinline__ float4 fetchA4(int mode, const float* A0, int m, int kk, int K){
    if (mode == 0) return ld4(&A0[m*K + kk]);
    if (kk < 512)  return ld4(&A0[(m<<9) + kk]);
    int o = (m<<9) + (kk - 512);
    if (mode == 1) return ld4(&g_h[o]);
    float4 a = ld4(&g_feats[o]); float4 w = ld4(&g_aw[o]);
    return make_float4(a.x*w.x, a.y*w.y, a.z*w.z, a.w*w.w);
}

// C[128,N] (+)= A[128,K] @ W[N,K]^T (+bias).  Tile: 128x64, BK=32, 256 thr, 8x4/thread.
// nsplit>1: split-K partial accumulated via atomicAdd (C must be pre-zeroed); bias added by split 0.
__device__ void gemm_dev(float (*As)[132], float (*Ws)[68],
                         int tile, int split, int nsplit, int mode,
                         const float* __restrict__ A0, const float* __restrict__ W,
                         const float* __restrict__ bias, float* __restrict__ C,
                         int N, int K)
{
    const int tid = threadIdx.x;
    const int n0 = tile * 64;
    const int kChunk = K / nsplit;
    const int kBeg = split * kChunk, kEnd = kBeg + kChunk;
    const int cx = tid & 15;   // col group 0..15 -> 4 cols
    const int ry = tid >> 4;   // row group 0..15 -> 8 rows

    float acc[8][4];
    for (int i=0;i<8;i++)
        for (int j=0;j<4;j++)
            acc[i][j]=0.f;

    for (int k0 = kBeg; k0 < kEnd; k0 += 32) {
        #pragma unroll
        for (int i=0;i<4;i++){                 // A tile 128x32
            int idx = tid + i*256;
            int m = idx >> 3, q = idx & 7;
            float4 v = fetchA4(mode, A0, m, k0 + 4*q, K);
            As[4*q+0][m]=v.x; As[4*q+1][m]=v.y; As[4*q+2][m]=v.z; As[4*q+3][m]=v.w;
        }
        #pragma unroll
        for (int i=0;i<2;i++){                 // W tile 64x32
            int idx = tid + i*256;
            int n = idx >> 3, q = idx & 7;
            float4 v = ld4(&W[(n0+n)*K + k0 + 4*q]);
            Ws[4*q+0][n]=v.x; Ws[4*q+1][n]=v.y; Ws[4*q+2][n]=v.z; Ws[4*q+3][n]=v.w;
        }
        __syncthreads();
        #pragma unroll
        for (int k=0;k<32;k++){
            float4 a0 = ld4(&As[k][8*ry]);
            float4 a1 = ld4(&As[k][8*ry+4]);
            float4 w  = ld4(&Ws[k][4*cx]);
            float av[8] = {a0.x,a0.y,a0.z,a0.w,a1.x,a1.y,a1.z,a1.w};
            float wv[4] = {w.x,w.y,w.z,w.w};
            #pragma unroll
            for(int i=0;i<8;i++)
              #pragma unroll
              for(int j=0;j<4;j++)
                acc[i][j] = fmaf(av[i], wv[j], acc[i][j]);
        }
        __syncthreads();
    }
    #pragma unroll
    for(int i=0;i<8;i++){
        int m = 8*ry + i;
        #pragma unroll
        for(int j=0;j<4;j++){
            int n = n0 + 4*cx + j;
            float v = acc[i][j];
            if (split == 0) v += bias[n];
            if (nsplit == 1) C[m*N + n] = v;
            else atomicAdd(&C[m*N + n], v);
        }
    }
}

#define GEMM_SHARED __shared__ float As[32][132]; __shared__ float Ws[32][68];

// ---------------- one-time kernels ----------------
__global__ void zero_init(){
    int stride = gridDim.x*blockDim.x;
    int i0 = blockIdx.x*blockDim.x + threadIdx.x;
    for (int i=i0;i<BB*EE;i+=stride)   g_f[i]=0.f;
    for (int i=i0;i<BB*HH;i+=stride)   g_al[i]=0.f;
    for (int i=i0;i<BB*3*HH;i+=stride) g_gh[i]=0.f;
}

__global__ void fc_kernel(const float* __restrict__ features,
                          const float* __restrict__ fcW, const float* __restrict__ fcb){
    GEMM_SHARED
    int tile = blockIdx.x & 7, split = blockIdx.x >> 3;   // 8 tiles x 16 splits = 128 blocks
    gemm_dev(As, Ws, tile, split, 16, 0, features, fcW, fcb, g_f, EE, FIN);
}

__global__ void bn_kernel(const float* __restrict__ gamma, const float* __restrict__ beta){
    int j = threadIdx.x;            // 512 threads, 1 block
    float s = 0.f;
    for (int b=0;b<BB;b++) s += g_f[b*EE + j];
    float mu = s * (1.f/BB);
    float v = 0.f;
    for (int b=0;b<BB;b++){ float d = g_f[b*EE+j]-mu; v += d*d; }
    float rstd = rsqrtf(v*(1.f/BB) + 1e-5f);
    float ga = gamma[j], be = beta[j];
    for (int b=0;b<BB;b++)
        g_feats[b*EE+j] = ga*(g_f[b*EE+j]-mu)*rstd + be;
}

__global__ void prep_kernel(const int* __restrict__ captions,
                            const float* __restrict__ embed_W,
                            const float* __restrict__ h0){
    int t = blockIdx.x;
    if (t < TT){
        float* dst = g_x + t*(BB*EE);
        for (int idx = threadIdx.x; idx < BB*EE; idx += blockDim.x){
            int b = idx >> 9, e = idx & 511;
            float v;
            if (t == 0) v = g_feats[idx];
            else { int cap = captions[b*TT + (t-1)]; v = embed_W[cap*EE + e]; }
            dst[idx] = v;
        }
    } else {
        for (int idx = threadIdx.x; idx < BB*HH; idx += blockDim.x)
            g_h[idx] = h0[idx];
    }
}

// ---------------- per-step kernels ----------------
// K1: attn logits (blocks 0..63) + Whh gemm (blocks 64..159); also zero g_inp for K2.
__global__ void step_k1(const float* __restrict__ attn_W, const float* __restrict__ attn_b,
                        const float* __restrict__ whh, const float* __restrict__ bhh, int t){
    GEMM_SHARED
    for (int idx = blockIdx.x*blockDim.x + threadIdx.x; idx < BB*HH; idx += gridDim.x*blockDim.x)
        g_inp[idx] = 0.f;
    const float* x = g_x + t*(BB*EE);
    if (blockIdx.x < 64) {
        int tile = blockIdx.x & 7, split = blockIdx.x >> 3;     // 8 tiles x 8 splits, K=1024
        gemm_dev(As, Ws, tile, split, 8, 1, x, attn_W, attn_b, g_al, HH, 1024);
    } else {
        int i = blockIdx.x - 64;                                 // 24 tiles x 4 splits, K=512
        int tile = i % 24, split = i / 24;
        gemm_dev(As, Ws, tile, split, 4, 0, g_h, whh, bhh, g_gh, 3*HH, HH);
    }
}

__global__ void step_softmax(){
    __shared__ float red[256];
    int b = blockIdx.x, tid = threadIdx.x;
    float v0 = g_al[b*512 + tid], v1 = g_al[b*512 + 256 + tid];
    float m = fmaxf(v0, v1);
    red[tid] = m; __syncthreads();
    for (int s=128; s>0; s>>=1){ if(tid<s) red[tid] = fmaxf(red[tid], red[tid+s]); __syncthreads(); }
    float mx = red[0]; __syncthreads();
    float e0 = expf(v0-mx), e1 = expf(v1-mx);
    red[tid] = e0+e1; __syncthreads();
    for (int s=128; s>0; s>>=1){ if(tid<s) red[tid]+=red[tid+s]; __syncthreads(); }
    float inv = 1.f/red[0];
    g_aw[b*512+tid]     = e0*inv;
    g_aw[b*512+256+tid] = e1*inv;
}

// K2: inp = [x, feats*aw] @ comb_W^T + b; also zero g_gx for K3a.
__global__ void step_k2(const float* __restrict__ comb_W, const float* __restrict__ comb_b, int t){
    GEMM_SHARED
    for (int idx = blockIdx.x*blockDim.x + threadIdx.x; idx < BB*3*HH; idx += gridDim.x*blockDim.x)
        g_gx[idx] = 0.f;
    const float* x = g_x + t*(BB*EE);
    int tile = blockIdx.x & 7, split = blockIdx.x >> 3;   // 8 tiles x 8 splits, K=1024
    gemm_dev(As, Ws, tile, split, 8, 2, x, comb_W, comb_b, g_inp, HH, 1024);
}

__global__ void step_k3a(const float* __restrict__ wih, const float* __restrict__ bih){
    GEMM_SHARED
    int tile = blockIdx.x % 24, split = blockIdx.x / 24;  // 24 tiles x 4 splits, K=512
    gemm_dev(As, Ws, tile, split, 4, 0, g_inp, wih, bih, g_gx, 3*HH, HH);
}

// K3b: GRU combine; writes h, hiddens(d_out), packed; re-zeroes g_al/g_gh for next step.
__global__ void step_k3b(float* __restrict__ out_hidden, int t){
    int idx = blockIdx.x*blockDim.x + threadIdx.x;        // 256x256 = 65536 exact
    int b = idx >> 9, j = idx & 511;
    int g = b*1536 + j;
    float xr = g_gx[g], xz = g_gx[g+512], xn = g_gx[g+1024];
    float hr = g_gh[g], hz = g_gh[g+512], hn = g_gh[g+1024];
    float hx = g_h[idx];
    float r = 1.f/(1.f+expf(-(xr+hr)));
    float z = 1.f/(1.f+expf(-(xz+hz)));
    float nt = tanhf(xn + r*hn);
    float h = (1.f - z)*nt + z*hx;
    g_h[idx] = h;
    out_hidden[b*(TT*HH) + t*HH + j] = h;
    g_packed[(t*BB + b)*HH + j] = h;
    g_al[idx] = 0.f;
    g_gh[g] = 0.f; g_gh[g+512] = 0.f; g_gh[g+1024] = 0.f;
}

// ---------------- final logits GEMM + log_softmax ----------------
__global__ __launch_bounds__(256,2) void out_gemm(const float* __restrict__ outW,
                                                  const float* __restrict__ outb,
                                                  float* __restrict__ logits){
    __shared__ float As[16][132];
    __shared__ float Bs[16][132];
    int tid = threadIdx.x;
    int n0 = blockIdx.x * 128;
    int m0 = blockIdx.y * 128;
    int tx = tid & 15, ty = tid >> 4;
    float acc[8][8];
    for (int i=0;i<8;i++)
        for (int j=0;j<8;j++)
            acc[i][j]=0.f;

    for (int k0=0;k0<512;k0+=16){
        #pragma unroll
        for (int i=0;i<2;i++){
            int idx = tid + i*256;
            int m = idx >> 2, q = idx & 3;
            float4 v = ld4(&g_packed[(m0+m)*512 + k0 + 4*q]);
            As[4*q+0][m]=v.x; As[4*q+1][m]=v.y; As[4*q+2][m]=v.z; As[4*q+3][m]=v.w;
            int n = n0 + m;
            float4 w = (n < VV) ? ld4(&outW[n*512 + k0 + 4*q]) : make_float4(0.f,0.f,0.f,0.f);
            Bs[4*q+0][m]=w.x; Bs[4*q+1][m]=w.y; Bs[4*q+2][m]=w.z; Bs[4*q+3][m]=w.w;
        }
        __syncthreads();
        #pragma unroll
        for (int k=0;k<16;k++){
            float4 a0=ld4(&As[k][8*ty]), a1=ld4(&As[k][8*ty+4]);
            float4 b0=ld4(&Bs[k][8*tx]), b1=ld4(&Bs[k][8*tx+4]);
            float av[8]={a0.x,a0.y,a0.z,a0.w,a1.x,a1.y,a1.z,a1.w};
            float bv[8]={b0.x,b0.y,b0.z,b0.w,b1.x,b1.y,b1.z,b1.w};
            #pragma unroll
            for(int i=0;i<8;i++)
              #pragma unroll
              for(int j=0;j<8;j++)
                acc[i][j] = fmaf(av[i], bv[j], acc[i][j]);
        }
        __syncthreads();
    }
    #pragma unroll
    for (int i=0;i<8;i++){
        int row = m0 + 8*ty + i;
        #pragma unroll
        for (int j=0;j<8;j++){
            int col = n0 + 8*tx + j;
            if (col < VV) logits[row*VV + col] = acc[i][j] + outb[col];
        }
    }
}

__global__ void lsm_kernel(float* __restrict__ logits){
    __shared__ float buf[VV];
    __shared__ float red[256];
    int row = blockIdx.x, tid = threadIdx.x;
    float* p = logits + row*VV;
    float m = -1e30f;
    for (int j=tid;j<VV;j+=256){ float v = p[j]; buf[j]=v; m = fmaxf(m,v); }
    red[tid]=m; __syncthreads();
    for (int s=128;s;s>>=1){ if(tid<s) red[tid]=fmaxf(red[tid],red[tid+s]); __syncthreads(); }
    float mx = red[0]; __syncthreads();
    float s=0.f;
    for (int j=tid;j<VV;j+=256) s += expf(buf[j]-mx);
    red[tid]=s; __syncthreads();
    for (int st=128;st;st>>=1){ if(tid<st) red[tid]+=red[tid+st]; __syncthreads(); }
    float lse = mx + logf(red[0]);
    for (int j=tid;j<VV;j+=256) p[j] = buf[j]-lse;
}

// ---------------- launch ----------------
extern "C" void kernel_launch(void* const* d_in, const int* in_sizes, int n_in,
                              void* d_out, int out_size){
    const float* features = (const float*)d_in[0];
    const int*   captions = (const int*)  d_in[1];
    const float* h0       = (const float*)d_in[2];
    /* d_in[3] = lengths (constant 64) */
    const float* embed_W  = (const float*)d_in[4];
    const float* fc_W     = (const float*)d_in[5];
    const float* fc_b     = (const float*)d_in[6];
    const float* bn_gamma = (const float*)d_in[7];
    const float* bn_beta  = (const float*)d_in[8];
    const float* attn_W   = (const float*)d_in[9];
    const float* attn_b   = (const float*)d_in[10];
    const float* comb_W   = (const float*)d_in[11];
    const float* comb_b   = (const float*)d_in[12];
    const float* gru_Wih  = (const float*)d_in[13];
    const float* gru_Whh  = (const float*)d_in[14];
    const float* gru_bih  = (const float*)d_in[15];
    const float* gru_bhh  = (const float*)d_in[16];
    const float* out_W    = (const float*)d_in[17];
    const float* out_b    = (const float*)d_in[18];

    float* out     = (float*)d_out;
    float* logits  = out;                       // [8192, 10000]
    float* hiddens = out + (size_t)TB*VV;       // [128, 64, 512]

    zero_init<<<128,256>>>();
    fc_kernel<<<128,256>>>(features, fc_W, fc_b);
    bn_kernel<<<1,512>>>(bn_gamma, bn_beta);
    prep_kernel<<<TT+1,256>>>(captions, embed_W, h0);
    for (int t=0;t<TT;t++){
        step_k1<<<160,256>>>(attn_W, attn_b, gru_Whh, gru_bhh, t);
        step_softmax<<<128,256>>>();
        step_k2<<<64,256>>>(comb_W, comb_b, t);
        step_k3a<<<96,256>>>(gru_Wih, gru_bih);
        step_k3b<<<256,256>>>(hiddens, t);
    }
    out_gemm<<<dim3(79,64),256>>>(out_W, out_b, logits);
    lsm_kernel<<<TB,256>>>(logits);
}

// round 8
// speedup vs baseline: 1.4848x; 1.4848x over previous
#include <cuda_runtime.h>
#include <cuda_bf16.h>
#include <math.h>
#include <stdint.h>

#define BB 128
#define TT 64
#define EE 512
#define HH 512
#define VV 10000
#define FIN 2048
#define TB (TT*BB)   /* 8192 */
#define NT 79        /* N tiles of 128 covering 10000 (padded to 10112) */

// ---------------- scratch (static device globals; no runtime alloc) ----------------
__device__ float g_f[BB*EE];
__device__ float g_feats[BB*EE];
__device__ float g_x[TT*BB*EE];
__device__ float g_h[BB*HH];
__device__ float g_al[BB*HH];
__device__ float g_aw[BB*HH];
__device__ float g_inp[BB*HH];
__device__ float g_gh[BB*3*HH];
__device__ float g_gx[BB*3*HH];
__device__ float g_packed[TB*HH];
__device__ __nv_bfloat16 g_pk16[TB*512];
__device__ __nv_bfloat16 g_w16[NT*128*512];

__device__ __forceinline__ float4 ld4(const float* p){ return *(const float4*)p; }

__device__ __forceinline__ uint32_t smem_u32(const void* p){
    uint32_t a;
    asm("{ .reg .u64 t; cvta.to.shared.u64 t, %1; cvt.u32.u64 %0, t; }" : "=r"(a) : "l"(p));
    return a;
}
__device__ __forceinline__ void ldm4(uint32_t* r, uint32_t addr){
    asm volatile("ldmatrix.sync.aligned.m8n8.x4.shared.b16 {%0,%1,%2,%3}, [%4];"
        : "=r"(r[0]),"=r"(r[1]),"=r"(r[2]),"=r"(r[3]) : "r"(addr));
}
__device__ __forceinline__ void mma16816(float* c, const uint32_t* a, uint32_t b0, uint32_t b1){
    asm volatile("mma.sync.aligned.m16n8k16.row.col.f32.bf16.bf16.f32 "
        "{%0,%1,%2,%3}, {%4,%5,%6,%7}, {%8,%9}, {%0,%1,%2,%3};"
        : "+f"(c[0]),"+f"(c[1]),"+f"(c[2]),"+f"(c[3])
        : "r"(a[0]),"r"(a[1]),"r"(a[2]),"r"(a[3]), "r"(b0),"r"(b1));
}

// ---------------- small fp32 GEMM (recurrence) ----------------
__device__ __forceinline__ float4 fetchA4(int mode, const float* A0, int m, int kk, int K){
    if (mode == 0) return ld4(&A0[m*K + kk]);
    if (kk < 512)  return ld4(&A0[(m<<9) + kk]);
    int o = (m<<9) + (kk - 512);
    if (mode == 1) return ld4(&g_h[o]);
    float4 a = ld4(&g_feats[o]); float4 w = ld4(&g_aw[o]);
    return make_float4(a.x*w.x, a.y*w.y, a.z*w.z, a.w*w.w);
}

__device__ void gemm_dev(float (*As)[132], float (*Ws)[68],
                         int tile, int split, int nsplit, int mode,
                         const float* __restrict__ A0, const float* __restrict__ W,
                         const float* __restrict__ bias, float* __restrict__ C,
                         int N, int K)
{
    const int tid = threadIdx.x;
    const int n0 = tile * 64;
    const int kChunk = K / nsplit;
    const int kBeg = split * kChunk, kEnd = kBeg + kChunk;
    const int cx = tid & 15;
    const int ry = tid >> 4;

    float acc[8][4];
    for (int i=0;i<8;i++)
        for (int j=0;j<4;j++)
            acc[i][j]=0.f;

    for (int k0 = kBeg; k0 < kEnd; k0 += 32) {
        #pragma unroll
        for (int i=0;i<4;i++){
            int idx = tid + i*256;
            int m = idx >> 3, q = idx & 7;
            float4 v = fetchA4(mode, A0, m, k0 + 4*q, K);
            As[4*q+0][m]=v.x; As[4*q+1][m]=v.y; As[4*q+2][m]=v.z; As[4*q+3][m]=v.w;
        }
        #pragma unroll
        for (int i=0;i<2;i++){
            int idx = tid + i*256;
            int n = idx >> 3, q = idx & 7;
            float4 v = ld4(&W[(n0+n)*K + k0 + 4*q]);
            Ws[4*q+0][n]=v.x; Ws[4*q+1][n]=v.y; Ws[4*q+2][n]=v.z; Ws[4*q+3][n]=v.w;
        }
        __syncthreads();
        #pragma unroll
        for (int k=0;k<32;k++){
            float4 a0 = ld4(&As[k][8*ry]);
            float4 a1 = ld4(&As[k][8*ry+4]);
            float4 w  = ld4(&Ws[k][4*cx]);
            float av[8] = {a0.x,a0.y,a0.z,a0.w,a1.x,a1.y,a1.z,a1.w};
            float wv[4] = {w.x,w.y,w.z,w.w};
            #pragma unroll
            for(int i=0;i<8;i++)
              #pragma unroll
              for(int j=0;j<4;j++)
                acc[i][j] = fmaf(av[i], wv[j], acc[i][j]);
        }
        __syncthreads();
    }
    #pragma unroll
    for(int i=0;i<8;i++){
        int m = 8*ry + i;
        #pragma unroll
        for(int j=0;j<4;j++){
            int n = n0 + 4*cx + j;
            float v = acc[i][j];
            if (split == 0) v += bias[n];
            if (nsplit == 1) C[m*N + n] = v;
            else atomicAdd(&C[m*N + n], v);
        }
    }
}

#define GEMM_SHARED __shared__ float As[32][132]; __shared__ float Ws[32][68];

// ---------------- one-time kernels ----------------
__global__ void zero_init(){
    int stride = gridDim.x*blockDim.x;
    int i0 = blockIdx.x*blockDim.x + threadIdx.x;
    for (int i=i0;i<BB*EE;i+=stride)   g_f[i]=0.f;
    for (int i=i0;i<BB*HH;i+=stride)   g_al[i]=0.f;
    for (int i=i0;i<BB*3*HH;i+=stride) g_gh[i]=0.f;
}

__global__ void cvt_w(const float* __restrict__ outW){
    int stride = gridDim.x*blockDim.x;
    for (int i = blockIdx.x*blockDim.x + threadIdx.x; i < NT*128*512; i += stride){
        int r = i >> 9;
        g_w16[i] = __float2bfloat16(r < VV ? outW[i] : 0.f);
    }
}

__global__ void cvt_pk(){
    int stride = gridDim.x*blockDim.x;
    for (int i = blockIdx.x*blockDim.x + threadIdx.x; i < TB*512; i += stride)
        g_pk16[i] = __float2bfloat16(g_packed[i]);
}

__global__ void fc_kernel(const float* __restrict__ features,
                          const float* __restrict__ fcW, const float* __restrict__ fcb){
    GEMM_SHARED
    int tile = blockIdx.x & 7, split = blockIdx.x >> 3;
    gemm_dev(As, Ws, tile, split, 16, 0, features, fcW, fcb, g_f, EE, FIN);
}

__global__ void bn_kernel(const float* __restrict__ gamma, const float* __restrict__ beta){
    int j = threadIdx.x;
    float s = 0.f;
    for (int b=0;b<BB;b++) s += g_f[b*EE + j];
    float mu = s * (1.f/BB);
    float v = 0.f;
    for (int b=0;b<BB;b++){ float d = g_f[b*EE+j]-mu; v += d*d; }
    float rstd = rsqrtf(v*(1.f/BB) + 1e-5f);
    float ga = gamma[j], be = beta[j];
    for (int b=0;b<BB;b++)
        g_feats[b*EE+j] = ga*(g_f[b*EE+j]-mu)*rstd + be;
}

__global__ void prep_kernel(const int* __restrict__ captions,
                            const float* __restrict__ embed_W,
                            const float* __restrict__ h0){
    int stride = gridDim.x*blockDim.x;
    for (int gi = blockIdx.x*blockDim.x + threadIdx.x; gi < TT*BB*EE; gi += stride){
        int t = gi >> 16;          // BB*EE = 65536
        int idx = gi & 65535;
        int b = idx >> 9, e = idx & 511;
        float v;
        if (t == 0) v = g_feats[idx];
        else { int cap = captions[b*TT + (t-1)]; v = embed_W[cap*EE + e]; }
        g_x[gi] = v;
    }
    for (int i = blockIdx.x*blockDim.x + threadIdx.x; i < BB*HH; i += stride)
        g_h[i] = h0[i];
}

// ---------------- per-step kernels ----------------
__global__ void step_k1(const float* __restrict__ attn_W, const float* __restrict__ attn_b,
                        const float* __restrict__ whh, const float* __restrict__ bhh, int t){
    GEMM_SHARED
    for (int idx = blockIdx.x*blockDim.x + threadIdx.x; idx < BB*HH; idx += gridDim.x*blockDim.x)
        g_inp[idx] = 0.f;
    const float* x = g_x + t*(BB*EE);
    if (blockIdx.x < 64) {
        int tile = blockIdx.x & 7, split = blockIdx.x >> 3;
        gemm_dev(As, Ws, tile, split, 8, 1, x, attn_W, attn_b, g_al, HH, 1024);
    } else {
        int i = blockIdx.x - 64;
        int tile = i % 24, split = i / 24;
        gemm_dev(As, Ws, tile, split, 4, 0, g_h, whh, bhh, g_gh, 3*HH, HH);
    }
}

__global__ void step_softmax(){
    __shared__ float red[256];
    int b = blockIdx.x, tid = threadIdx.x;
    float v0 = g_al[b*512 + tid], v1 = g_al[b*512 + 256 + tid];
    float m = fmaxf(v0, v1);
    red[tid] = m; __syncthreads();
    for (int s=128; s>0; s>>=1){ if(tid<s) red[tid] = fmaxf(red[tid], red[tid+s]); __syncthreads(); }
    float mx = red[0]; __syncthreads();
    float e0 = expf(v0-mx), e1 = expf(v1-mx);
    red[tid] = e0+e1; __syncthreads();
    for (int s=128; s>0; s>>=1){ if(tid<s) red[tid]+=red[tid+s]; __syncthreads(); }
    float inv = 1.f/red[0];
    g_aw[b*512+tid]     = e0*inv;
    g_aw[b*512+256+tid] = e1*inv;
}

__global__ void step_k2(const float* __restrict__ comb_W, const float* __restrict__ comb_b, int t){
    GEMM_SHARED
    for (int idx = blockIdx.x*blockDim.x + threadIdx.x; idx < BB*3*HH; idx += gridDim.x*blockDim.x)
        g_gx[idx] = 0.f;
    const float* x = g_x + t*(BB*EE);
    int tile = blockIdx.x & 7, split = blockIdx.x >> 3;
    gemm_dev(As, Ws, tile, split, 8, 2, x, comb_W, comb_b, g_inp, HH, 1024);
}

__global__ void step_k3a(const float* __restrict__ wih, const float* __restrict__ bih){
    GEMM_SHARED
    int tile = blockIdx.x % 24, split = blockIdx.x / 24;
    gemm_dev(As, Ws, tile, split, 4, 0, g_inp, wih, bih, g_gx, 3*HH, HH);
}

__global__ void step_k3b(float* __restrict__ out_hidden, int t){
    int idx = blockIdx.x*blockDim.x + threadIdx.x;
    int b = idx >> 9, j = idx & 511;
    int g = b*1536 + j;
    float xr = g_gx[g], xz = g_gx[g+512], xn = g_gx[g+1024];
    float hr = g_gh[g], hz = g_gh[g+512], hn = g_gh[g+1024];
    float hx = g_h[idx];
    float r = 1.f/(1.f+expf(-(xr+hr)));
    float z = 1.f/(1.f+expf(-(xz+hz)));
    float nt = tanhf(xn + r*hn);
    float h = (1.f - z)*nt + z*hx;
    g_h[idx] = h;
    out_hidden[b*(TT*HH) + t*HH + j] = h;
    g_packed[(t*BB + b)*HH + j] = h;
    g_al[idx] = 0.f;
    g_gh[g] = 0.f; g_gh[g+512] = 0.f; g_gh[g+1024] = 0.f;
}

// ---------------- HMMA (mma.sync bf16) logits GEMM ----------------
// C[8192,10000] = packed(bf16) @ outW(bf16)^T + bias, fp32 accum.
// CTA tile 128x128, 8 warps (4M x 2N), warp tile 32x64, K chunks of 64.
#define APAD 72   /* bf16 row stride: 144B -> 4-bank shift per row, ldmatrix conflict-free */

__global__ __launch_bounds__(256) void out_gemm_mma(const float* __restrict__ outb,
                                                    float* __restrict__ logits){
    __shared__ __nv_bfloat16 Asm[128][APAD];
    __shared__ __nv_bfloat16 Bsm[128][APAD];
    __shared__ float s_bias[128];

    const int tid = threadIdx.x;
    const int lane = tid & 31, wid = tid >> 5;
    const int wm = wid & 3, wn = wid >> 2;      // 4 x 2 warp grid
    const int m0 = blockIdx.y * 128, n0 = blockIdx.x * 128;

    if (tid < 128){ int n = n0 + tid; s_bias[tid] = (n < VV) ? outb[n] : 0.f; }

    float acc[2][8][4];
    #pragma unroll
    for (int i=0;i<2;i++)
        #pragma unroll
        for (int j=0;j<8;j++)
            #pragma unroll
            for (int q=0;q<4;q++) acc[i][j][q]=0.f;

    const __nv_bfloat16* Ag = g_pk16 + (size_t)m0 * 512;
    const __nv_bfloat16* Bg = g_w16  + (size_t)n0 * 512;

    // per-thread ldmatrix source addresses (row/khalf pattern shared by A and B)
    const int lrow = lane & 15, lkh = (lane >> 4) * 8;

    for (int c = 0; c < 8; c++){
        // load 128x64 bf16 chunk of A and B into smem (4 uint4 per thread each)
        #pragma unroll
        for (int j = 0; j < 4; j++){
            int idx = tid + j*256;
            int r = idx >> 3, cv = idx & 7;
            *(uint4*)&Asm[r][cv*8] = *(const uint4*)(Ag + (size_t)r*512 + c*64 + cv*8);
            *(uint4*)&Bsm[r][cv*8] = *(const uint4*)(Bg + (size_t)r*512 + c*64 + cv*8);
        }
        __syncthreads();
        #pragma unroll
        for (int ks = 0; ks < 4; ks++){
            int kk = ks*16;
            uint32_t a[2][4];
            #pragma unroll
            for (int mt=0; mt<2; mt++){
                uint32_t ad = smem_u32(&Asm[wm*32 + mt*16 + lrow][kk + lkh]);
                ldm4(a[mt], ad);
            }
            uint32_t b[4][4];
            #pragma unroll
            for (int nt=0; nt<4; nt++){
                uint32_t bd = smem_u32(&Bsm[wn*64 + nt*16 + lrow][kk + lkh]);
                ldm4(b[nt], bd);
            }
            #pragma unroll
            for (int mt=0; mt<2; mt++)
                #pragma unroll
                for (int nt=0; nt<4; nt++){
                    mma16816(acc[mt][nt*2+0], a[mt], b[nt][0], b[nt][2]);
                    mma16816(acc[mt][nt*2+1], a[mt], b[nt][1], b[nt][3]);
                }
        }
        __syncthreads();
    }

    // epilogue: thread holds (row = lane>>2 [+8], col = (lane&3)*2 [+1]) per 16x8 tile
    const int r0 = lane >> 2, c2 = (lane & 3) * 2;
    #pragma unroll
    for (int mt=0; mt<2; mt++){
        int row = m0 + wm*32 + mt*16 + r0;
        #pragma unroll
        for (int nt=0; nt<8; nt++){
            int lcol = wn*64 + nt*8 + c2;
            int col  = n0 + lcol;
            if (col < VV){
                float2 v0, v1;
                v0.x = acc[mt][nt][0] + s_bias[lcol];
                v0.y = acc[mt][nt][1] + s_bias[lcol+1];
                v1.x = acc[mt][nt][2] + s_bias[lcol];
                v1.y = acc[mt][nt][3] + s_bias[lcol+1];
                *(float2*)&logits[(size_t)row * VV + col] = v0;
                *(float2*)&logits[(size_t)(row+8) * VV + col] = v1;
            }
        }
    }
}

__global__ void lsm_kernel(float* __restrict__ logits){
    __shared__ float buf[VV];
    __shared__ float red[256];
    int row = blockIdx.x, tid = threadIdx.x;
    float* p = logits + (size_t)row*VV;
    float m = -1e30f;
    for (int j=tid;j<VV;j+=256){ float v = p[j]; buf[j]=v; m = fmaxf(m,v); }
    red[tid]=m; __syncthreads();
    for (int s=128;s;s>>=1){ if(tid<s) red[tid]=fmaxf(red[tid],red[tid+s]); __syncthreads(); }
    float mx = red[0]; __syncthreads();
    float s=0.f;
    for (int j=tid;j<VV;j+=256) s += expf(buf[j]-mx);
    red[tid]=s; __syncthreads();
    for (int st=128;st;st>>=1){ if(tid<st) red[tid]+=red[tid+st]; __syncthreads(); }
    float lse = mx + logf(red[0]);
    for (int j=tid;j<VV;j+=256) p[j] = buf[j]-lse;
}

// ---------------- launch ----------------
extern "C" void kernel_launch(void* const* d_in, const int* in_sizes, int n_in,
                              void* d_out, int out_size){
    const float* features = (const float*)d_in[0];
    const int*   captions = (const int*)  d_in[1];
    const float* h0       = (const float*)d_in[2];
    const float* embed_W  = (const float*)d_in[4];
    const float* fc_W     = (const float*)d_in[5];
    const float* fc_b     = (const float*)d_in[6];
    const float* bn_gamma = (const float*)d_in[7];
    const float* bn_beta  = (const float*)d_in[8];
    const float* attn_W   = (const float*)d_in[9];
    const float* attn_b   = (const float*)d_in[10];
    const float* comb_W   = (const float*)d_in[11];
    const float* comb_b   = (const float*)d_in[12];
    const float* gru_Wih  = (const float*)d_in[13];
    const float* gru_Whh  = (const float*)d_in[14];
    const float* gru_bih  = (const float*)d_in[15];
    const float* gru_bhh  = (const float*)d_in[16];
    const float* out_W    = (const float*)d_in[17];
    const float* out_b    = (const float*)d_in[18];

    float* out     = (float*)d_out;
    float* logits  = out;                       // [8192, 10000]
    float* hiddens = out + (size_t)TB*VV;       // [128, 64, 512]

    zero_init<<<128,256>>>();
    cvt_w<<<2048,256>>>(out_W);
    fc_kernel<<<128,256>>>(features, fc_W, fc_b);
    bn_kernel<<<1,512>>>(bn_gamma, bn_beta);
    prep_kernel<<<1024,256>>>(captions, embed_W, h0);
    for (int t=0;t<TT;t++){
        step_k1<<<160,256>>>(attn_W, attn_b, gru_Whh, gru_bhh, t);
        step_softmax<<<128,256>>>();
        step_k2<<<64,256>>>(comb_W, comb_b, t);
        step_k3a<<<96,256>>>(gru_Wih, gru_bih);
        step_k3b<<<256,256>>>(hiddens, t);
    }
    cvt_pk<<<2048,256>>>();
    out_gemm_mma<<<dim3(NT,64),256>>>(out_b, logits);
    lsm_kernel<<<TB,256>>>(logits);
}